// round 13
// baseline (speedup 1.0000x reference)
#include <cuda_runtime.h>

// ---------------------------------------------------------------------------
// SSIM (16,3,512,512) fp32, 11x11 Gaussian (sigma=1.5), zero pad, global mean.
// R13: 2 columns/thread, NT=256 (8 warps). Warp-private halo rows (74 slots of
// (S,D) float2 pairs); taps loaded as 6x ld.shared.v2.u64 (16B) per thread
// covering BOTH columns' windows -> smem reads per column halved.
// In-SMEM Hadamard transform (x,y)->(S,D) pipelined one row ahead (row ir+1
// transformed during phase ir). cp.async depth-3 over 8 rotating buffers.
// Static mod-11 f32x2 vertical ring per column (reset folded into MUL2).
// ---------------------------------------------------------------------------

#define IMW     512
#define IMH     512
#define NT      256                 // one thread per 2 columns
#define TH      171                 // output rows per band (3 bands cover 512)
#define NBANDS  3
#define NPLANES 48                  // 16 * 3
#define NBLOCKS (NPLANES * NBANDS)  // 144 CTAs -> single wave
#define SSIM_C1 0.0001f
#define SSIM_C2 0.0009f

typedef unsigned long long ull;

__device__ float        g_partials[NBLOCKS];
__device__ unsigned int g_count;    // zero-init; reset by last block each run

#define CPA4_O(daddr, sptr, D, S) \
    asm volatile("cp.async.ca.shared.global [%0+" #D "], [%1+" #S "], 4;" \
                 :: "r"(daddr), "l"(sptr))
#define CPA_COMMIT() asm volatile("cp.async.commit_group;" ::: "memory")
#define CPA_WAIT2()  asm volatile("cp.async.wait_group 2;"  ::: "memory")
#define CPA_WAIT1()  asm volatile("cp.async.wait_group 1;"  ::: "memory")

#define LDS128(d0, d1, a) \
    asm volatile("ld.shared.v2.u64 {%0,%1}, [%2];" \
                 : "=l"(d0), "=l"(d1) : "r"(a))
#define ADD2(d, a, b) \
    asm("add.rn.f32x2 %0, %1, %2;" : "=l"(d) : "l"(a), "l"(b))
#define MUL2(d, a, b) \
    asm("mul.rn.f32x2 %0, %1, %2;" : "=l"(d) : "l"(a), "l"(b))
#define FMA2ACC(acc, a, b) \
    asm("fma.rn.f32x2 %0, %1, %2, %0;" : "+l"(acc) : "l"(a), "l"(b))
#define UNPACK2(lo, hi, s) \
    asm("mov.b64 {%0, %1}, %2;" : "=f"(lo), "=f"(hi) : "l"(s))

// Transform this lane's 2 main slots (16B at A) from (x,y) to (x+y, x-y).
#define TRANSMAIN(A) do {                                                     \
    float x0_, y0_, x1_, y1_;                                                 \
    asm volatile("ld.shared.v4.f32 {%0,%1,%2,%3}, [%4];"                      \
                 : "=f"(x0_), "=f"(y0_), "=f"(x1_), "=f"(y1_) : "r"(A));      \
    const float s0_ = x0_ + y0_, d0_ = x0_ - y0_;                             \
    const float s1_ = x1_ + y1_, d1_ = x1_ - y1_;                             \
    asm volatile("st.shared.v4.f32 [%0], {%1,%2,%3,%4};"                      \
                 :: "r"(A), "f"(s0_), "f"(d0_), "f"(s1_), "f"(d1_));          \
} while (0)
// Transform tail slot (8B at A).
#define TRANSTAIL(A) do {                                                     \
    float xt_, yt_;                                                           \
    asm volatile("ld.shared.v2.f32 {%0,%1}, [%2];"                            \
                 : "=f"(xt_), "=f"(yt_) : "r"(A));                            \
    const float st_ = xt_ + yt_, dt_ = xt_ - yt_;                             \
    asm volatile("st.shared.v2.f32 [%0], {%1,%2};"                            \
                 :: "r"(A), "f"(st_), "f"(dt_));                              \
} while (0)

#define TRANSROW(rn) do {                                                     \
    const unsigned ta_ = sbu + (unsigned)((rn) & 7) * BSTRIDE;                \
    TRANSMAIN(ta_);                                                           \
    if (tailst) TRANSTAIL(ta_ + tailoff);                                     \
} while (0)

// Load the 12 taps (both columns' windows) for row ir from buffer ir&7.
#define ROWLOAD(ir_) do {                                                     \
    const unsigned rb_ = sbu + (unsigned)((ir_) & 7) * BSTRIDE;               \
    _Pragma("unroll")                                                         \
    for (int i = 0; i < 6; ++i) LDS128(tp[2*i], tp[2*i+1], rb_ + 16u * i);    \
} while (0)

// SSIM extraction from packed ring slots (one column).
#define EXTRACT(PQ, SD) do {                                                  \
    float p_, q_, sv_, dv_;                                                   \
    UNPACK2(p_, q_, PQ);                                                      \
    UNPACK2(sv_, dv_, SD);                                                    \
    const float a2_ = p_ * p_;                                                \
    const float b2_ = q_ * q_;                                                \
    const float U_  = a2_ + b2_;                                              \
    const float V_  = a2_ - b2_;                                              \
    const float M_  = sv_ + dv_;                                              \
    const float N2_ = sv_ - dv_;                                              \
    const float t1_ = 0.5f * V_ + SSIM_C1;                                    \
    const float t2_ = 0.5f * (N2_ - V_) + SSIM_C2;                            \
    const float t3_ = 0.5f * U_ + SSIM_C1;                                    \
    const float t4_ = 0.5f * (M_ - U_) + SSIM_C2;                             \
    ssum += __fdividef(t1_ * t2_, t3_ * t4_);                                 \
} while (0)

// h-conv (both columns, shared squares) + ring + extraction.
// P must be a compile-time constant == ir_ mod 11. Taps already in tp[].
#define ROWMATH(P, ir_) do {                                                  \
    ull sq[12];                                                               \
    _Pragma("unroll")                                                         \
    for (int j = 0; j < 12; ++j) MUL2(sq[j], tp[j], tp[j]);                   \
    ull hlA, hsA, hlB, hsB;                                                   \
    MUL2(hlA, tp[5], W2[5]);                                                  \
    MUL2(hsA, sq[5], W2[5]);                                                  \
    MUL2(hlB, tp[6], W2[5]);                                                  \
    MUL2(hsB, sq[6], W2[5]);                                                  \
    _Pragma("unroll")                                                         \
    for (int k = 0; k < 5; ++k) {                                             \
        ull ab;                                                               \
        ADD2(ab, tp[k], tp[10 - k]);                                          \
        FMA2ACC(hlA, ab, W2[k]);                                              \
        ADD2(ab, sq[k], sq[10 - k]);                                          \
        FMA2ACC(hsA, ab, W2[k]);                                              \
        ADD2(ab, tp[k + 1], tp[11 - k]);                                      \
        FMA2ACC(hlB, ab, W2[k]);                                              \
        ADD2(ab, sq[k + 1], sq[11 - k]);                                      \
        FMA2ACC(hsB, ab, W2[k]);                                              \
    }                                                                         \
    _Pragma("unroll")                                                         \
    for (int s = 0; s < 11; ++s) {                                            \
        const int d = ((P) - s + 11) % 11;      /* compile-time */            \
        if (s == (P)) {     /* tap d==0: new output -> overwrite (reset) */   \
            MUL2(APQa[s], hlA, W2[0]);                                        \
            MUL2(ASDa[s], hsA, W2[0]);                                        \
            MUL2(APQb[s], hlB, W2[0]);                                        \
            MUL2(ASDb[s], hsB, W2[0]);                                        \
        } else {                                                              \
            FMA2ACC(APQa[s], hlA, W2[d]);                                     \
            FMA2ACC(ASDa[s], hsA, W2[d]);                                     \
            FMA2ACC(APQb[s], hlB, W2[d]);                                     \
            FMA2ACC(ASDb[s], hsB, W2[d]);                                     \
        }                                                                     \
    }                                                                         \
    const int e_ = ((P) + 1) % 11;              /* compile-time */            \
    if ((ir_) >= 10) {          /* output row m = ir-10 is real */            \
        EXTRACT(APQa[e_], ASDa[e_]);                                          \
        EXTRACT(APQb[e_], ASDb[e_]);                                          \
    }                                                                         \
} while (0)

// Guard-free phase (rows 0..175; fill rows <= 178 <= nrows-2; trans <= 176).
#define PHASEF(P, IRV) do {                                                   \
    const int irf_ = (IRV);                                                   \
    ull tp[12];                                                               \
    ROWLOAD(irf_);                                                            \
    FILLF(irf_ + 3);                                                          \
    CPA_COMMIT();                                                             \
    CPA_WAIT2();               /* rows <= irf_+1 complete */                  \
    TRANSROW(irf_ + 1);                                                       \
    __syncwarp();                                                             \
    ROWMATH(P, irf_);                                                         \
} while (0)

// Guarded tail phase (rows 176..nrows-1).
#define PHASET(P, IRV) do {                                                   \
    const int irt_ = (IRV);                                                   \
    if (irt_ < nrows) {                                                       \
        ull tp[12];                                                           \
        ROWLOAD(irt_);                                                        \
        if (irt_ + 3 < nrows) FILLF(irt_ + 3);                                \
        CPA_COMMIT();                                                         \
        CPA_WAIT2();                                                          \
        if (irt_ + 1 < nrows) TRANSROW(irt_ + 1);                             \
        __syncwarp();                                                         \
        ROWMATH(P, irt_);                                                     \
    }                                                                         \
} while (0)

__global__ void __launch_bounds__(NT, 1)
ssim_main(const float* __restrict__ img1, const float* __restrict__ img2,
          float* __restrict__ out)
{
    // Normalized 1D Gaussian, sigma=1.5, 11 taps
    const float W[11] = {
        0.00102838f, 0.00759874f, 0.03600077f, 0.10936069f, 0.21300553f,
        0.26601180f,
        0.21300553f, 0.10936069f, 0.03600077f, 0.00759874f, 0.00102838f
    };
    // Duplicated 64-bit weight pairs (w|w) for f32x2 ops
    ull W2[11];
#pragma unroll
    for (int k = 0; k < 11; ++k) {
        const unsigned u = __float_as_uint(W[k]);
        W2[k] = ((ull)u << 32) | (ull)u;
    }

    const int band  = blockIdx.x;           // 0..2
    const int plane = blockIdx.y;           // 0..47
    const int t     = threadIdx.x;          // 0..255
    const int l     = t & 31;               // lane
    const int w     = t >> 5;               // warp (0..7), covers 64 columns
    const int r0    = band * TH;
    const int rows  = (IMH - r0 < TH) ? (IMH - r0) : TH;   // 171/171/170
    const int nrows = rows + 10;            // 181/181/180
    const int pbase = plane * (IMW * IMH);

    // Warp-private 8-deep rotating halo rows.
    // seg[buf][w][j], j in [0,74): pixel pair at image column 64*w - 5 + j.
    // Filled raw (x,y) by cp.async; Hadamard-transformed in place to (S,D).
    __shared__ __align__(16) float2 seg[8][8][76];

    // Static rings (packed), per column: slot s <-> output rows m % 11 == s.
    ull APQa[11], ASDa[11], APQb[11], ASDb[11];
#pragma unroll
    for (int j = 0; j < 11; ++j) {
        APQa[j] = 0ULL; ASDa[j] = 0ULL; APQb[j] = 0ULL; ASDb[j] = 0ULL;
    }

    // Columns owned by this lane: outA = 64w+2l, outB = outA+1.
    // Main fill slots j = 2l, 2l+1  <-> cols 64w-5+2l, 64w-4+2l.
    // Tail fill slot  j = 64+l (l<10) <-> col 64w+59+l.
    const int  cA0    = 64 * w + 2 * l - 5;       // col of slot 2l
    const bool ok0    = (cA0 >= 0);               // (never >= IMW)
    const bool ok1    = (cA0 + 1 >= 0);
    const int  ct     = 64 * w + 59 + l;          // col of slot 64+l
    const bool tailst = (l < 10);
    const bool tailok = tailst && (ct < IMW);

    // Base pointers (row 0) for this lane's fill columns.
    const float* bpA1 = img1 + pbase + cA0;
    const float* bpA2 = img2 + pbase + cA0;
    const float* bpT1 = img1 + pbase + ct;
    const float* bpT2 = img2 + pbase + ct;

    // u32 shared address of this lane's main slot pair in buffer 0.
    unsigned sbu;
    asm("{ .reg .u64 tt; cvta.to.shared.u64 tt, %1; cvt.u32.u64 %0, tt; }"
        : "=r"(sbu) : "l"(&seg[0][w][2 * l]));
    const unsigned BSTRIDE = 8u * 76u * 8u;       // bytes per buffer (4864)
    const unsigned tailoff = 512u - 8u * (unsigned)l;  // slot 64+l vs slot 2l

    auto FILLF = [&](int rn) {
        const int gr = r0 - 5 + rn;               // global row (0-pad if OOB)
        const unsigned d = sbu + (unsigned)(rn & 7) * BSTRIDE;
        if ((unsigned)gr < (unsigned)IMH) {
            const int off = gr * IMW;
            const float* pA1 = bpA1 + off;
            const float* pA2 = bpA2 + off;
            if (ok0) { CPA4_O(d, pA1, 0, 0);  CPA4_O(d, pA2, 4, 0); }
            if (ok1) { CPA4_O(d, pA1, 8, 4);  CPA4_O(d, pA2, 12, 4); }
            if (tailok) {
                const unsigned dt = d + tailoff;
                CPA4_O(dt, bpT1 + off, 0, 0);
                CPA4_O(dt, bpT2 + off, 4, 0);
            }
        } else {
            const float z = 0.f;
            asm volatile("st.shared.v4.f32 [%0], {%1,%1,%1,%1};"
                         :: "r"(d), "f"(z));
            if (tailst)
                asm volatile("st.shared.v2.f32 [%0], {%1,%1};"
                             :: "r"(d + tailoff), "f"(z));
        }
    };

    // Pre-zero slots never written by cp.async (col-invalid); all 8 buffers.
#pragma unroll
    for (int b = 0; b < 8; ++b) {
        const unsigned d = sbu + (unsigned)b * BSTRIDE;
        const float z = 0.f;
        if (!ok0)
            asm volatile("st.shared.v2.f32 [%0], {%1,%1};" :: "r"(d), "f"(z));
        if (!ok1)
            asm volatile("st.shared.v2.f32 [%0+8], {%1,%1};" :: "r"(d), "f"(z));
        if (tailst && !tailok)
            asm volatile("st.shared.v2.f32 [%0], {%1,%1};"
                         :: "r"(d + tailoff), "f"(z));
    }

    // Prologue: rows 0,1,2 in flight; rows 0,1 complete; row 0 transformed.
    FILLF(0); CPA_COMMIT();
    FILLF(1); CPA_COMMIT();
    FILLF(2); CPA_COMMIT();
    CPA_WAIT1();                 // rows 0,1 done
    TRANSROW(0);
    __syncwarp();

    float ssum = 0.f;

    // 16 guard-free blocks: rows 0..175.
#pragma unroll 1
    for (int base = 0; base < 176; base += 11) {
#pragma unroll
        for (int q = 0; q < 11; ++q) {
            PHASEF(q, base + q);
        }
    }
    // Guarded tail: rows 176..nrows-1 (176 % 11 == 0 -> P == q).
    {
#pragma unroll
        for (int q = 0; q < 11; ++q) {
            PHASET(q, 176 + q);
        }
    }

    // ---- deterministic block reduction ----
    __syncthreads();
#pragma unroll
    for (int off = 16; off; off >>= 1)
        ssum += __shfl_xor_sync(0xffffffffu, ssum, off);

    __shared__ float wsum[8];
    __shared__ bool  islast;
    if (l == 0) wsum[w] = ssum;
    __syncthreads();
    if (t == 0) {
        float v = 0.f;
#pragma unroll
        for (int i = 0; i < 8; ++i) v += wsum[i];
        g_partials[plane * NBANDS + band] = v;
        __threadfence();
        const unsigned n = atomicAdd(&g_count, 1u);
        islast = (n == (unsigned)(NBLOCKS - 1));
    }
    __syncthreads();

    // ---- last CTA: fixed-order (deterministic) final reduction ----
    if (islast) {
        __threadfence();
        float v = (t < NBLOCKS) ? g_partials[t] : 0.f;
#pragma unroll
        for (int off = 16; off; off >>= 1)
            v += __shfl_xor_sync(0xffffffffu, v, off);
        if (l == 0) wsum[w] = v;
        __syncthreads();
        if (t == 0) {
            float s = 0.f;
#pragma unroll
            for (int i = 0; i < 8; ++i) s += wsum[i];
            out[0] = s * (1.0f / 12582912.0f);  // / (16*3*512*512)
            g_count = 0u;                        // reset for next graph replay
        }
    }
}

extern "C" void kernel_launch(void* const* d_in, const int* in_sizes, int n_in,
                              void* d_out, int out_size)
{
    const float* img1 = (const float*)d_in[0];
    const float* img2 = (const float*)d_in[1];
    (void)in_sizes; (void)n_in; (void)out_size;

    dim3 grid(NBANDS, NPLANES);
    ssim_main<<<grid, NT>>>(img1, img2, (float*)d_out);
}